// round 1
// baseline (speedup 1.0000x reference)
#include <cuda_runtime.h>
#include <cstdint>

// GRU decoder, H=4096, T=2048 (read from device), persistent single-kernel
// with software grid barrier. fp32 baseline: DRAM-bound on W_hh streaming.

#define HDIM 4096
#define IN_DIM 400
#define OROWS 401
#define NOUT 400
#define WARPS_PER_BLOCK 28
#define NTHREADS (WARPS_PER_BLOCK * 32)

// ---- device scratch (no allocations allowed) ----
__device__ float g_h[2][HDIM];        // double-buffered hidden state
__device__ float g_gx[3 * HDIM];      // W_ih @ relu(x) + b_ih (per-launch constant)
__device__ unsigned g_cnt;            // grid barrier arrive counter
__device__ unsigned g_gen;            // grid barrier generation (monotonic across replays)

__device__ __forceinline__ float warp_sum(float v) {
#pragma unroll
    for (int o = 16; o; o >>= 1) v += __shfl_xor_sync(0xffffffffu, v, o);
    return v;
}

// Sense-reversing grid barrier. Requires all blocks co-resident
// (grid == #SMs, 1 block/SM via __launch_bounds__).
__device__ __forceinline__ void grid_sync() {
    __syncthreads();
    if (threadIdx.x == 0) {
        __threadfence();
        unsigned gen = *(volatile unsigned*)&g_gen;
        unsigned nblk = gridDim.x;
        if (atomicAdd(&g_cnt, 1u) == nblk - 1u) {
            atomicExch(&g_cnt, 0u);
            __threadfence();
            atomicAdd(&g_gen, 1u);
        } else {
            while (*(volatile unsigned*)&g_gen == gen) { __nanosleep(64); }
        }
        __threadfence();
    }
    __syncthreads();
}

__device__ __forceinline__ float sigmoidf_(float x) { return 1.0f / (1.0f + expf(-x)); }

__global__ void __launch_bounds__(NTHREADS, 1)
decoder_persistent_kernel(const float* __restrict__ start,
                          const float* __restrict__ enc,
                          const float* __restrict__ W_ih,
                          const float* __restrict__ W_hh,
                          const float* __restrict__ b_ih,
                          const float* __restrict__ b_hh,
                          const float* __restrict__ W_out,
                          const float* __restrict__ b_out,
                          const int*   __restrict__ maxlen_ptr,
                          float* __restrict__ out)
{
    __shared__ float h_s[HDIM];

    const int lane   = threadIdx.x & 31;
    const int warp   = threadIdx.x >> 5;
    const int gwarp  = blockIdx.x * WARPS_PER_BLOCK + warp;
    const int gwarps = gridDim.x * WARPS_PER_BLOCK;
    const int T = maxlen_ptr ? *maxlen_ptr : 2048;

    // ---- init: h0 = encoder_hidden ----
    for (int idx = blockIdx.x * blockDim.x + threadIdx.x; idx < HDIM;
         idx += gridDim.x * blockDim.x)
        g_h[0][idx] = enc[idx];

    // ---- gx = W_ih @ relu(start) + b_ih (once per launch) ----
    for (int r = gwarp; r < 3 * HDIM; r += gwarps) {
        const float* wr = W_ih + (size_t)r * IN_DIM;
        float acc = 0.f;
        for (int k = lane; k < IN_DIM; k += 32) {
            float x = start[k];
            x = x > 0.f ? x : 0.f;
            acc += wr[k] * x;
        }
        acc = warp_sum(acc);
        if (lane == 0) g_gx[r] = acc + b_ih[r];
    }
    grid_sync();

    // Stage-B row mapping: spread the 401 W_out rows evenly over all SMs.
    int spread = gwarps / OROWS;
    if (spread < 1) spread = 1;
    int brow = -1;
    if ((gwarp % spread) == 0 && (gwarp / spread) < OROWS) brow = gwarp / spread;

    // ---- main recurrence ----
    for (int t = 0; t < T; t++) {
        const float* __restrict__ hc = g_h[t & 1];
        float* __restrict__ hn = g_h[(t + 1) & 1];

        // Stage h_cur into shared memory
        for (int idx = threadIdx.x; idx < HDIM; idx += NTHREADS)
            h_s[idx] = hc[idx];
        __syncthreads();

        // Stage A: each warp computes one h_new[i] (3 dot products + gates)
        for (int i = gwarp; i < HDIM; i += gwarps) {
            const float4* w0 = (const float4*)(W_hh + (size_t)i * HDIM);
            const float4* w1 = (const float4*)(W_hh + ((size_t)i + HDIM) * HDIM);
            const float4* w2 = (const float4*)(W_hh + ((size_t)i + 2 * HDIM) * HDIM);
            const float4* h4 = (const float4*)h_s;
            float a0 = 0.f, a1 = 0.f, a2 = 0.f;
#pragma unroll 2
            for (int k = lane; k < HDIM / 4; k += 32) {
                float4 hv = h4[k];
                float4 x0 = w0[k];
                float4 x1 = w1[k];
                float4 x2 = w2[k];
                a0 += x0.x * hv.x; a0 += x0.y * hv.y; a0 += x0.z * hv.z; a0 += x0.w * hv.w;
                a1 += x1.x * hv.x; a1 += x1.y * hv.y; a1 += x1.z * hv.z; a1 += x1.w * hv.w;
                a2 += x2.x * hv.x; a2 += x2.y * hv.y; a2 += x2.z * hv.z; a2 += x2.w * hv.w;
            }
            a0 = warp_sum(a0);
            a1 = warp_sum(a1);
            a2 = warp_sum(a2);
            if (lane == 0) {
                float ghr = a0 + b_hh[i];
                float ghz = a1 + b_hh[i + HDIM];
                float ghn = a2 + b_hh[i + 2 * HDIM];
                float r = sigmoidf_(g_gx[i] + ghr);
                float z = sigmoidf_(g_gx[i + HDIM] + ghz);
                float n = tanhf(g_gx[i + 2 * HDIM] + r * ghn);
                hn[i] = (1.f - z) * n + z * h_s[i];
            }
        }

        grid_sync();  // h_new globally visible

        // Stage B: o = W_out @ h_new + b_out; out=tanh(o[:400]), stop=sigmoid(o[400])
        if (brow >= 0) {
            const float4* wr = (const float4*)(W_out + (size_t)brow * HDIM);
            const float4* h4 = (const float4*)hn;
            float acc = 0.f;
#pragma unroll 2
            for (int k = lane; k < HDIM / 4; k += 32) {
                float4 w = wr[k];
                float4 hv = h4[k];
                acc += w.x * hv.x; acc += w.y * hv.y; acc += w.z * hv.z; acc += w.w * hv.w;
            }
            acc = warp_sum(acc);
            if (lane == 0) {
                float o = acc + b_out[brow];
                if (brow < NOUT)
                    out[(size_t)t * NOUT + brow] = tanhf(o);
                else
                    out[(size_t)T * NOUT + t] = sigmoidf_(o);  // stops after outputs block
            }
        }
        // No barrier needed here: next step's Stage A only reads h_new (ready)
        // and overwrites the buffer whose last cross-block readers were the
        // pre-barrier smem copies of this step.
    }
}

extern "C" void kernel_launch(void* const* d_in, const int* in_sizes, int n_in,
                              void* d_out, int out_size) {
    (void)in_sizes; (void)out_size;

    int dev = 0;
    cudaGetDevice(&dev);
    int sm = 148;
    cudaDeviceGetAttribute(&sm, cudaDevAttrMultiProcessorCount, dev);
    if (sm < 1) sm = 148;
    if (sm > 512) sm = 512;

    const float* start = (const float*)d_in[0];
    const float* enc   = (const float*)d_in[1];
    const float* W_ih  = (const float*)d_in[2];
    const float* W_hh  = (const float*)d_in[3];
    const float* b_ih  = (const float*)d_in[4];
    const float* b_hh  = (const float*)d_in[5];
    const float* W_out = (const float*)d_in[6];
    const float* b_out = (const float*)d_in[7];
    const int* maxlen  = (n_in > 8) ? (const int*)d_in[8] : nullptr;

    decoder_persistent_kernel<<<sm, NTHREADS>>>(
        start, enc, W_ih, W_hh, b_ih, b_hh, W_out, b_out, maxlen, (float*)d_out);
}

// round 2
// speedup vs baseline: 3.0559x; 3.0559x over previous
#include <cuda_runtime.h>
#include <cuda_fp16.h>
#include <cstdint>

// GRU decoder, H=4096, T=2048. Persistent single kernel + software grid barrier.
// Round 2: convert W_hh/W_out to fp16 scratch once per launch -> 100.7 MB
// working set fits in L2 (~126 MB) -> steps run at LTS bandwidth, not HBM.

#define HDIM 4096
#define IN_DIM 400
#define OROWS 401
#define NOUT 400
#define WARPS_PER_BLOCK 28
#define NTHREADS (WARPS_PER_BLOCK * 32)

// ---- device scratch (static: no runtime allocations allowed) ----
__device__ __half g_whh_h[(size_t)3 * HDIM * HDIM];   // 100.7 MB fp16 W_hh
__device__ __half g_wout_h[(size_t)OROWS * HDIM];     // 3.3 MB fp16 W_out
__device__ float g_h[2][HDIM];                        // double-buffered hidden state
__device__ float g_gx[3 * HDIM];                      // W_ih @ relu(x) + b_ih
__device__ unsigned g_cnt;                            // grid barrier arrive counter
__device__ unsigned g_gen;                            // grid barrier generation

__device__ __forceinline__ float warp_sum(float v) {
#pragma unroll
    for (int o = 16; o; o >>= 1) v += __shfl_xor_sync(0xffffffffu, v, o);
    return v;
}

// Sense-reversing grid barrier; all blocks co-resident (grid == #SMs, 1 blk/SM).
__device__ __forceinline__ void grid_sync() {
    __syncthreads();
    if (threadIdx.x == 0) {
        __threadfence();
        unsigned gen = *(volatile unsigned*)&g_gen;
        unsigned nblk = gridDim.x;
        if (atomicAdd(&g_cnt, 1u) == nblk - 1u) {
            atomicExch(&g_cnt, 0u);
            __threadfence();
            atomicAdd(&g_gen, 1u);
        } else {
            while (*(volatile unsigned*)&g_gen == gen) { __nanosleep(32); }
        }
        __threadfence();
    }
    __syncthreads();
}

__device__ __forceinline__ float sigmoidf_(float x) { return 1.0f / (1.0f + expf(-x)); }

// dot of 8 fp16 weights (as uint4) with 8 fp32 h values, fp32 accumulate
__device__ __forceinline__ float dot8(uint4 u, float4 hA, float4 hB) {
    float2 p; float s0 = 0.f, s1 = 0.f;
    p = __half22float2(*(const __half2*)&u.x); s0 += p.x * hA.x; s1 += p.y * hA.y;
    p = __half22float2(*(const __half2*)&u.y); s0 += p.x * hA.z; s1 += p.y * hA.w;
    p = __half22float2(*(const __half2*)&u.z); s0 += p.x * hB.x; s1 += p.y * hB.y;
    p = __half22float2(*(const __half2*)&u.w); s0 += p.x * hB.z; s1 += p.y * hB.w;
    return s0 + s1;
}

__global__ void __launch_bounds__(NTHREADS, 1)
decoder_persistent_kernel(const float* __restrict__ start,
                          const float* __restrict__ enc,
                          const float* __restrict__ W_ih,
                          const float* __restrict__ W_hh,
                          const float* __restrict__ b_ih,
                          const float* __restrict__ b_hh,
                          const float* __restrict__ W_out,
                          const float* __restrict__ b_out,
                          const int*   __restrict__ maxlen_ptr,
                          float* __restrict__ out)
{
    __shared__ float h_s[HDIM];

    const int lane   = threadIdx.x & 31;
    const int warp   = threadIdx.x >> 5;
    const int gwarp  = blockIdx.x * WARPS_PER_BLOCK + warp;
    const int gwarps = gridDim.x * WARPS_PER_BLOCK;
    const int gtid    = blockIdx.x * NTHREADS + threadIdx.x;
    const int gthreads = gridDim.x * NTHREADS;
    const int T = maxlen_ptr ? *maxlen_ptr : 2048;

    // ---- convert W_hh, W_out to fp16 scratch (every launch; deterministic) ----
    {
        const size_t total = (size_t)3 * HDIM * HDIM;   // multiple of 4
        for (size_t idx = (size_t)gtid * 4; idx < total; idx += (size_t)gthreads * 4) {
            float4 v = *(const float4*)(W_hh + idx);
            __half2* dst = (__half2*)(g_whh_h + idx);
            dst[0] = __floats2half2_rn(v.x, v.y);
            dst[1] = __floats2half2_rn(v.z, v.w);
        }
        const size_t ototal = (size_t)OROWS * HDIM;     // multiple of 4
        for (size_t idx = (size_t)gtid * 4; idx < ototal; idx += (size_t)gthreads * 4) {
            float4 v = *(const float4*)(W_out + idx);
            __half2* dst = (__half2*)(g_wout_h + idx);
            dst[0] = __floats2half2_rn(v.x, v.y);
            dst[1] = __floats2half2_rn(v.z, v.w);
        }
    }

    // ---- init: h0 = encoder_hidden ----
    for (int idx = gtid; idx < HDIM; idx += gthreads)
        g_h[0][idx] = enc[idx];

    // ---- gx = W_ih @ relu(start) + b_ih (once per launch, fp32) ----
    for (int r = gwarp; r < 3 * HDIM; r += gwarps) {
        const float* wr = W_ih + (size_t)r * IN_DIM;
        float acc = 0.f;
        for (int k = lane; k < IN_DIM; k += 32) {
            float x = start[k];
            x = x > 0.f ? x : 0.f;
            acc += wr[k] * x;
        }
        acc = warp_sum(acc);
        if (lane == 0) g_gx[r] = acc + b_ih[r];
    }
    grid_sync();

    // Stage-B row mapping: spread 401 W_out rows evenly across all SMs
    int spread = gwarps / OROWS;
    if (spread < 1) spread = 1;
    int brow = -1;
    if ((gwarp % spread) == 0 && (gwarp / spread) < OROWS) brow = gwarp / spread;

    // ---- main recurrence ----
    for (int t = 0; t < T; t++) {
        const float* __restrict__ hc = g_h[t & 1];
        float* __restrict__ hn = g_h[(t + 1) & 1];

        // stage h_cur into shared memory
        for (int idx = threadIdx.x; idx < HDIM; idx += NTHREADS)
            h_s[idx] = hc[idx];
        __syncthreads();

        // Stage A: one warp per output i, three fp16 row dots + gate math
        for (int i = gwarp; i < HDIM; i += gwarps) {
            const uint4* w0 = (const uint4*)(g_whh_h + (size_t)i * HDIM);
            const uint4* w1 = (const uint4*)(g_whh_h + ((size_t)i + HDIM) * HDIM);
            const uint4* w2 = (const uint4*)(g_whh_h + ((size_t)i + 2 * HDIM) * HDIM);
            const float4* h4 = (const float4*)h_s;
            float a0 = 0.f, a1 = 0.f, a2 = 0.f;
#pragma unroll 4
            for (int k = lane; k < HDIM / 8; k += 32) {   // 16 iterations
                uint4 u0 = w0[k];
                uint4 u1 = w1[k];
                uint4 u2 = w2[k];
                float4 hA = h4[2 * k];
                float4 hB = h4[2 * k + 1];
                a0 += dot8(u0, hA, hB);
                a1 += dot8(u1, hA, hB);
                a2 += dot8(u2, hA, hB);
            }
            a0 = warp_sum(a0);
            a1 = warp_sum(a1);
            a2 = warp_sum(a2);
            if (lane == 0) {
                float ghr = a0 + b_hh[i];
                float ghz = a1 + b_hh[i + HDIM];
                float ghn = a2 + b_hh[i + 2 * HDIM];
                float r = sigmoidf_(g_gx[i] + ghr);
                float z = sigmoidf_(g_gx[i + HDIM] + ghz);
                float n = tanhf(g_gx[i + 2 * HDIM] + r * ghn);
                hn[i] = (1.f - z) * n + z * h_s[i];
            }
        }

        grid_sync();  // h_new globally visible

        // Stage B: o = W_out @ h_new + b_out (fp16 weights, fp32 h/accum)
        if (brow >= 0) {
            const uint4* wr = (const uint4*)(g_wout_h + (size_t)brow * HDIM);
            const float4* h4 = (const float4*)hn;
            float acc = 0.f;
#pragma unroll 4
            for (int k = lane; k < HDIM / 8; k += 32) {
                uint4 u = wr[k];
                float4 hA = h4[2 * k];
                float4 hB = h4[2 * k + 1];
                acc += dot8(u, hA, hB);
            }
            acc = warp_sum(acc);
            if (lane == 0) {
                float o = acc + b_out[brow];
                if (brow < NOUT)
                    out[(size_t)t * NOUT + brow] = tanhf(o);
                else
                    out[(size_t)T * NOUT + t] = sigmoidf_(o);
            }
        }
        // no second barrier: next Stage A reads hn (ready) and overwrites the
        // buffer whose last cross-block readers were this step's smem copies.
    }
}

extern "C" void kernel_launch(void* const* d_in, const int* in_sizes, int n_in,
                              void* d_out, int out_size) {
    (void)in_sizes; (void)out_size;

    int dev = 0;
    cudaGetDevice(&dev);
    int sm = 148;
    cudaDeviceGetAttribute(&sm, cudaDevAttrMultiProcessorCount, dev);
    if (sm < 1) sm = 148;
    if (sm > 512) sm = 512;

    const float* start = (const float*)d_in[0];
    const float* enc   = (const float*)d_in[1];
    const float* W_ih  = (const float*)d_in[2];
    const float* W_hh  = (const float*)d_in[3];
    const float* b_ih  = (const float*)d_in[4];
    const float* b_hh  = (const float*)d_in[5];
    const float* W_out = (const float*)d_in[6];
    const float* b_out = (const float*)d_in[7];
    const int* maxlen  = (n_in > 8) ? (const int*)d_in[8] : nullptr;

    decoder_persistent_kernel<<<sm, NTHREADS>>>(
        start, enc, W_ih, W_hh, b_ih, b_hh, W_out, b_out, maxlen, (float*)d_out);
}